// round 11
// baseline (speedup 1.0000x reference)
#include <cuda_runtime.h>

#define NMAX 100000
#define EMAX 1600000
#define GNUM 64
#define HID  64
#define EDIM 16
#define OUTD 128

typedef unsigned long long ull;

// ---------------- static device scratch (no allocations allowed) ----------------
__device__ int   g_cnt[NMAX];
__device__ int   g_fill[NMAX];
__device__ int   g_off[NMAX + 1];
__device__ int   g_part[128];
__device__ int   g_csr_src[EMAX];
__device__ int   g_csr_eid[EMAX];
__device__ __align__(16) float g_ea_csr[(size_t)EMAX * EDIM];   // edge_attr gathered to CSR order
__device__ __align__(16) float g_loop_attr[NMAX * EDIM];
__device__ __align__(16) float g_xl[NMAX * HID];
__device__ __align__(16) float g_xr[NMAX * HID];
__device__ __align__(16) float g_x1[NMAX * HID];
__device__ __align__(16) float g_x2[NMAX * HID];
__device__ float g_gsum[GNUM * HID];
__device__ int   g_gcnt[GNUM];

// ---------------- f32x2 helpers ----------------
__device__ __forceinline__ ull pack2(float a, float b) {
    ull v; asm("mov.b64 %0, {%1,%2};" : "=l"(v) : "f"(a), "f"(b)); return v;
}
__device__ __forceinline__ float2 unpack2(ull v) {
    float2 r; asm("mov.b64 {%0,%1}, %2;" : "=f"(r.x), "=f"(r.y) : "l"(v)); return r;
}
__device__ __forceinline__ ull ffma2(ull a, ull b, ull c) {
    ull d; asm("fma.rn.f32x2 %0, %1, %2, %3;" : "=l"(d) : "l"(a), "l"(b), "l"(c)); return d;
}
__device__ __forceinline__ ull mul2(ull a, ull b) {
    ull d; asm("mul.rn.f32x2 %0, %1, %2;" : "=l"(d) : "l"(a), "l"(b)); return d;
}
__device__ __forceinline__ float lrelu(float v) {
    return fmaf(0.8f, fmaxf(v, 0.f), 0.2f * v);   // v>0 ? v : 0.2v
}

// ---------------- zero scratch ----------------
__global__ void zero_setup(int n) {
    int i = blockIdx.x * blockDim.x + threadIdx.x;
    if (i < n) { g_cnt[i] = 0; g_fill[i] = 0; }
    if (i < GNUM * HID) g_gsum[i] = 0.f;
    if (i < GNUM) g_gcnt[i] = 0;
}

// ---------------- degree histogram ----------------
__global__ void count_kernel(const int* __restrict__ dstA, int ne) {
    int e = blockIdx.x * blockDim.x + threadIdx.x;
    if (e < ne) atomicAdd(&g_cnt[dstA[e]], 1);
}

// ---------------- exclusive scan (3 kernels) ----------------
__global__ void scanA(int n) {
    __shared__ int s[1024];
    int t = threadIdx.x;
    int i = blockIdx.x * 1024 + t;
    int v = (i < n) ? g_cnt[i] : 0;
    s[t] = v;
    __syncthreads();
    for (int off = 1; off < 1024; off <<= 1) {
        int tmp = (t >= off) ? s[t - off] : 0;
        __syncthreads();
        s[t] += tmp;
        __syncthreads();
    }
    if (i < n) g_off[i] = s[t] - v;
    if (t == 1023) g_part[blockIdx.x] = s[1023];
}

__global__ void scanB(int nb, int n) {
    if (threadIdx.x == 0 && blockIdx.x == 0) {
        int run = 0;
        for (int b = 0; b < nb; b++) { int v = g_part[b]; g_part[b] = run; run += v; }
        g_off[n] = run;
    }
}

__global__ void scanC(int n) {
    int i = blockIdx.x * blockDim.x + threadIdx.x;
    if (i < n) g_off[i] += g_part[i >> 10];
}

// ---------------- CSR fill ----------------
__global__ void fill_kernel(const int* __restrict__ srcA, const int* __restrict__ dstA, int ne) {
    int e = blockIdx.x * blockDim.x + threadIdx.x;
    if (e >= ne) return;
    int d = dstA[e];
    int pos = g_off[d] + atomicAdd(&g_fill[d], 1);
    g_csr_src[pos] = srcA[e];
    g_csr_eid[pos] = e;
}

// ---------------- gather edge_attr into CSR order (float4 vectorized) ----------------
__global__ void gather_ea_kernel(const float* __restrict__ ea, int ne) {
    int i = blockIdx.x * blockDim.x + threadIdx.x;   // quad index over ne*4
    if (i >= ne * 4) return;
    int pos = i >> 2;          // CSR position
    int q   = i & 3;           // which float4 of the 16-attr row
    int eid = g_csr_eid[pos];
    const float4* src = reinterpret_cast<const float4*>(ea + (size_t)eid * EDIM);
    float4* dst = reinterpret_cast<float4*>(g_ea_csr + (size_t)pos * EDIM);
    dst[q] = src[q];
}

// ---------------- self-loop attr = mean of incoming edge attrs (sequential reads) ----
__global__ __launch_bounds__(256) void loop_attr_kernel(int n) {
    int t = threadIdx.x;
    int d = blockIdx.x * 8 + (t >> 5);
    if (d >= n) return;
    int l = t & 31;
    int k = l & 15;
    int half = l >> 4;
    int beg = g_off[d], deg = g_cnt[d];
    float acc = 0.f;
    for (int i = half; i < deg; i += 2) {
        acc += g_ea_csr[(size_t)(beg + i) * EDIM + k];
    }
    acc += __shfl_xor_sync(0xffffffffu, acc, 16);
    if (half == 0) {
        float inv = 1.f / fmaxf((float)deg, 1.f);
        g_loop_attr[d * EDIM + k] = acc * inv;
    }
}

// ---------------- xl = x@Wl + bl ; xr = x@Wr + br  (row-pair f32x2 packed) ----------------
__global__ __launch_bounds__(256) void gemm_kernel(
    const float* __restrict__ x0in,
    const float* __restrict__ Wl, const float* __restrict__ bl,
    const float* __restrict__ Wr, const float* __restrict__ br,
    int n, int layer)
{
    const float* __restrict__ xin = layer ? g_x1 : x0in;
    __shared__ float sWl[64 * 64];
    __shared__ float sWr[64 * 64];
    __shared__ __align__(16) float sx[64 * 68];   // [k][row], 272B stride
    int t = threadIdx.x;
    for (int i = t; i < 4096; i += 256) { sWl[i] = Wl[i]; sWr[i] = Wr[i]; }
    int row0 = blockIdx.x * 64;
    for (int idx = t; idx < 4096; idx += 256) {
        int r = idx >> 6, k = idx & 63;
        int rr = row0 + r;
        sx[k * 68 + r] = (rr < n) ? xin[rr * 64 + k] : 0.f;
    }
    __syncthreads();
    int c = t & 63, rq = t >> 6;
    float blc = bl[c], brc = br[c];
    ull bl2 = pack2(blc, blc), br2 = pack2(brc, brc);
    ull accL[8], accR[8];
#pragma unroll
    for (int j = 0; j < 8; j++) { accL[j] = bl2; accR[j] = br2; }
#pragma unroll 4
    for (int k = 0; k < 64; k++) {
        float wl = sWl[k * 64 + c];
        float wr = sWr[k * 64 + c];
        ull wl2 = pack2(wl, wl), wr2 = pack2(wr, wr);
        const ulonglong2* xp = reinterpret_cast<const ulonglong2*>(&sx[k * 68 + rq * 16]);
#pragma unroll
        for (int q = 0; q < 4; q++) {
            ulonglong2 xv = xp[q];
            accL[q * 2]     = ffma2(xv.x, wl2, accL[q * 2]);
            accL[q * 2 + 1] = ffma2(xv.y, wl2, accL[q * 2 + 1]);
            accR[q * 2]     = ffma2(xv.x, wr2, accR[q * 2]);
            accR[q * 2 + 1] = ffma2(xv.y, wr2, accR[q * 2 + 1]);
        }
    }
#pragma unroll
    for (int j = 0; j < 8; j++) {
        float2 vl = unpack2(accL[j]);
        float2 vr = unpack2(accR[j]);
        int r0 = row0 + rq * 16 + 2 * j;
        if (r0 < n)     { g_xl[r0 * 64 + c] = vl.x;       g_xr[r0 * 64 + c] = vr.x; }
        if (r0 + 1 < n) { g_xl[(r0 + 1) * 64 + c] = vl.y; g_xr[(r0 + 1) * 64 + c] = vr.y; }
    }
}

// ---------------- per-edge pre-reduction score for the lane's two channels ----------
__device__ __forceinline__ float edge_score(
    const ulonglong2* __restrict__ ap, float2 xl2, float2 xr2, float2 at,
    const ull* wp0, const ull* wp1)
{
    ulonglong2 qa = ap[0], qb = ap[1], qc = ap[2], qd = ap[3];
    ull a0 = 0ull, a1 = 0ull;
    a0 = ffma2(qa.x, wp0[0], a0); a1 = ffma2(qa.x, wp1[0], a1);
    a0 = ffma2(qa.y, wp0[1], a0); a1 = ffma2(qa.y, wp1[1], a1);
    a0 = ffma2(qb.x, wp0[2], a0); a1 = ffma2(qb.x, wp1[2], a1);
    a0 = ffma2(qb.y, wp0[3], a0); a1 = ffma2(qb.y, wp1[3], a1);
    a0 = ffma2(qc.x, wp0[4], a0); a1 = ffma2(qc.x, wp1[4], a1);
    a0 = ffma2(qc.y, wp0[5], a0); a1 = ffma2(qc.y, wp1[5], a1);
    a0 = ffma2(qd.x, wp0[6], a0); a1 = ffma2(qd.x, wp1[6], a1);
    a0 = ffma2(qd.y, wp0[7], a0); a1 = ffma2(qd.y, wp1[7], a1);
    float2 h0 = unpack2(a0), h1 = unpack2(a1);
    float e0 = h0.x + h0.y;
    float e1 = h1.x + h1.y;
    float m0 = lrelu(xl2.x + xr2.x + e0);
    float m1 = lrelu(xl2.y + xr2.y + e1);
    return fmaf(at.x, m0, at.y * m1);
}

// ---------------- fused GATv2 layer: score + online softmax + aggregate ----------------
// warp per node d; lane l owns channels (2l, 2l+1); head h = l>>3.
// edge loop hand-unrolled by 2 for ILP/MLP; pragma keeps ptxas from exploding regs.
__global__ __launch_bounds__(256) void fused_gat_layer(
    const float* __restrict__ We, const float* __restrict__ att,
    const float* __restrict__ bias, int n, int layer)
{
    int t = threadIdx.x;
    int d = blockIdx.x * 8 + (t >> 5);
    if (d >= n) return;
    int l = t & 31;

    ull wp0[8], wp1[8];
#pragma unroll
    for (int j = 0; j < 8; j++) {
        float2 wa = *reinterpret_cast<const float2*>(We + (2 * j)     * 64 + 2 * l);
        float2 wb = *reinterpret_cast<const float2*>(We + (2 * j + 1) * 64 + 2 * l);
        wp0[j] = pack2(wa.x, wb.x);
        wp1[j] = pack2(wa.y, wb.y);
    }
    float2 at  = *reinterpret_cast<const float2*>(att + 2 * l);
    float2 xr2 = unpack2(*reinterpret_cast<const ull*>(g_xr + d * 64 + 2 * l));

    int beg = g_off[d], deg = g_cnt[d];

    // ---- self-loop initializes online softmax state ----
    ull xl_self = *reinterpret_cast<const ull*>(g_xl + d * 64 + 2 * l);
    float p = edge_score(reinterpret_cast<const ulonglong2*>(g_loop_attr + d * 16),
                         unpack2(xl_self), xr2, at, wp0, wp1);
    p += __shfl_xor_sync(0xffffffffu, p, 1);
    p += __shfl_xor_sync(0xffffffffu, p, 2);
    p += __shfl_xor_sync(0xffffffffu, p, 4);
    float mx  = p;
    float den = 1.f;
    ull   acc = xl_self;

    const ulonglong2* eac = reinterpret_cast<const ulonglong2*>(g_ea_csr);

    int i = 0;
#pragma unroll 1
    for (; i + 2 <= deg; i += 2) {
        int s0 = g_csr_src[beg + i];
        int s1 = g_csr_src[beg + i + 1];
        ull xlu0 = *reinterpret_cast<const ull*>(g_xl + s0 * 64 + 2 * l);
        ull xlu1 = *reinterpret_cast<const ull*>(g_xl + s1 * 64 + 2 * l);
        float p0 = edge_score(eac + (size_t)(beg + i) * 4,     unpack2(xlu0), xr2, at, wp0, wp1);
        float p1 = edge_score(eac + (size_t)(beg + i + 1) * 4, unpack2(xlu1), xr2, at, wp0, wp1);
        p0 += __shfl_xor_sync(0xffffffffu, p0, 1);  p1 += __shfl_xor_sync(0xffffffffu, p1, 1);
        p0 += __shfl_xor_sync(0xffffffffu, p0, 2);  p1 += __shfl_xor_sync(0xffffffffu, p1, 2);
        p0 += __shfl_xor_sync(0xffffffffu, p0, 4);  p1 += __shfl_xor_sync(0xffffffffu, p1, 4);
        float pnew  = fmaxf(mx, fmaxf(p0, p1));
        float scale = __expf(mx - pnew);
        float z0    = __expf(p0 - pnew);
        float z1    = __expf(p1 - pnew);
        mx  = pnew;
        den = fmaf(den, scale, z0 + z1);
        acc = ffma2(acc, pack2(scale, scale), mul2(pack2(z0, z0), xlu0));
        acc = ffma2(pack2(z1, z1), xlu1, acc);
    }
    if (i < deg) {
        int s0 = g_csr_src[beg + i];
        ull xlu0 = *reinterpret_cast<const ull*>(g_xl + s0 * 64 + 2 * l);
        float p0 = edge_score(eac + (size_t)(beg + i) * 4, unpack2(xlu0), xr2, at, wp0, wp1);
        p0 += __shfl_xor_sync(0xffffffffu, p0, 1);
        p0 += __shfl_xor_sync(0xffffffffu, p0, 2);
        p0 += __shfl_xor_sync(0xffffffffu, p0, 4);
        float pnew  = fmaxf(mx, p0);
        float scale = __expf(mx - pnew);
        float z0    = __expf(p0 - pnew);
        mx  = pnew;
        den = fmaf(den, scale, z0);
        acc = ffma2(acc, pack2(scale, scale), mul2(pack2(z0, z0), xlu0));
    }

    float2 av = unpack2(acc);
    float inv = 1.f / den;
    float2 bv = *reinterpret_cast<const float2*>(bias + 2 * l);
    float o0 = fmaxf(fmaf(av.x, inv, bv.x), 0.f);
    float o1 = fmaxf(fmaf(av.y, inv, bv.y), 0.f);
    float* xout = layer ? g_x2 : g_x1;
    *reinterpret_cast<float2*>(xout + d * 64 + 2 * l) = make_float2(o0, o1);
}

// ---------------- mean pool (block-local smem accumulation) ----------------
__global__ __launch_bounds__(256) void pool_kernel(const int* __restrict__ batch, int n)
{
    __shared__ float sacc[GNUM * HID];
    __shared__ int scnt[GNUM];
    int t = threadIdx.x;
    for (int i = t; i < GNUM * HID; i += 256) sacc[i] = 0.f;
    if (t < GNUM) scnt[t] = 0;
    __syncthreads();
    int c = t & 63, sub = t >> 6;
    int start = blockIdx.x * 512;
    int end = min(start + 512, n);
    for (int i = start + sub; i < end; i += 4) {
        int b = batch[i];
        atomicAdd(&sacc[b * HID + c], g_x2[i * HID + c]);
        if (c == 0) atomicAdd(&scnt[b], 1);
    }
    __syncthreads();
    for (int i = t; i < GNUM * HID; i += 256) {
        float v = sacc[i];
        if (v != 0.f) atomicAdd(&g_gsum[i], v);
    }
    if (t < GNUM && scnt[t] != 0) atomicAdd(&g_gcnt[t], scnt[t]);
}

// ---------------- final MLP (one block per graph) ----------------
__global__ __launch_bounds__(128) void mlp_kernel(
    const float* __restrict__ W1, const float* __restrict__ b1,
    const float* __restrict__ W2, const float* __restrict__ b2,
    float* __restrict__ out)
{
    __shared__ float sg[HID];
    __shared__ float sh[OUTD];
    int g = blockIdx.x, t = threadIdx.x;
    if (t < HID) {
        float c = fmaxf((float)g_gcnt[g], 1.f);
        sg[t] = g_gsum[g * HID + t] / c;
    }
    __syncthreads();
    float acc = b1[t];
#pragma unroll
    for (int k = 0; k < HID; k++) acc = fmaf(sg[k], W1[k * OUTD + t], acc);
    sh[t] = fmaxf(acc, 0.f);
    __syncthreads();
    float acc2 = b2[t];
#pragma unroll
    for (int k = 0; k < OUTD; k++) acc2 = fmaf(sh[k], W2[k * OUTD + t], acc2);
    out[g * OUTD + t] = acc2;
}

// ---------------- launch ----------------
extern "C" void kernel_launch(void* const* d_in, const int* in_sizes, int n_in,
                              void* d_out, int out_size)
{
    const float* x0    = (const float*)d_in[0];
    const int*   ei    = (const int*)d_in[1];
    const float* ea    = (const float*)d_in[2];
    const int*   batch = (const int*)d_in[3];

    int n  = in_sizes[0] / HID;      // 100000
    int ne = in_sizes[1] / 2;        // edge_index is (2, E)
    if (n > NMAX) n = NMAX;
    if (ne > EMAX) ne = EMAX;

    const int* srcA = ei;
    const int* dstA = ei + ne;

    const float* Wl[2]   = { (const float*)d_in[4],  (const float*)d_in[11] };
    const float* blv[2]  = { (const float*)d_in[5],  (const float*)d_in[12] };
    const float* Wr[2]   = { (const float*)d_in[6],  (const float*)d_in[13] };
    const float* brv[2]  = { (const float*)d_in[7],  (const float*)d_in[14] };
    const float* We[2]   = { (const float*)d_in[8],  (const float*)d_in[15] };
    const float* att[2]  = { (const float*)d_in[9],  (const float*)d_in[16] };
    const float* bias[2] = { (const float*)d_in[10], (const float*)d_in[17] };
    const float* mW1 = (const float*)d_in[18];
    const float* mb1 = (const float*)d_in[19];
    const float* mW2 = (const float*)d_in[20];
    const float* mb2 = (const float*)d_in[21];
    float* out = (float*)d_out;

    int nb = (n + 1023) / 1024;

    zero_setup<<<(n + 255) / 256, 256>>>(n);
    count_kernel<<<(ne + 255) / 256, 256>>>(dstA, ne);
    scanA<<<nb, 1024>>>(n);
    scanB<<<1, 32>>>(nb, n);
    scanC<<<(n + 255) / 256, 256>>>(n);
    fill_kernel<<<(ne + 255) / 256, 256>>>(srcA, dstA, ne);
    gather_ea_kernel<<<(ne * 4 + 255) / 256, 256>>>(ea, ne);
    loop_attr_kernel<<<(n + 7) / 8, 256>>>(n);

    for (int layer = 0; layer < 2; layer++) {
        gemm_kernel<<<(n + 63) / 64, 256>>>(x0, Wl[layer], blv[layer], Wr[layer], brv[layer], n, layer);
        fused_gat_layer<<<(n + 7) / 8, 256>>>(We[layer], att[layer], bias[layer], n, layer);
    }

    pool_kernel<<<(n + 511) / 512, 256>>>(batch, n);
    mlp_kernel<<<GNUM, 128>>>(mW1, mb1, mW2, mb2, out);
}

// round 14
// speedup vs baseline: 1.0629x; 1.0629x over previous
#include <cuda_runtime.h>

#define NMAX 100000
#define EMAX 1600000
#define GNUM 64
#define HID  64
#define EDIM 16
#define OUTD 128
#define EPW  16   // edges (or nodes) per warp in scoring kernels

typedef unsigned long long ull;

// ---------------- static device scratch (no allocations allowed) ----------------
__device__ int   g_cnt[NMAX];
__device__ int   g_fill[NMAX];
__device__ int   g_off[NMAX + 1];
__device__ int   g_part[128];
__device__ int   g_csr_src[EMAX];
__device__ int   g_csr_dst[EMAX];
__device__ int   g_csr_eid[EMAX];
__device__ __align__(16) float g_ea_csr[(size_t)EMAX * EDIM];   // edge_attr in CSR order
__device__ __align__(16) float g_loop_attr[NMAX * EDIM];
__device__ __align__(16) float g_xl[NMAX * HID];
__device__ __align__(16) float g_xr[NMAX * HID];
__device__ __align__(16) float g_x1[NMAX * HID];
__device__ __align__(16) float g_x2[NMAX * HID];
__device__ __align__(16) float g_score[(size_t)EMAX * 4];       // per CSR position, 4 heads
__device__ __align__(16) float g_score_self[NMAX * 4];
__device__ float g_gsum[GNUM * HID];
__device__ int   g_gcnt[GNUM];

// ---------------- f32x2 helpers ----------------
__device__ __forceinline__ ull pack2(float a, float b) {
    ull v; asm("mov.b64 %0, {%1,%2};" : "=l"(v) : "f"(a), "f"(b)); return v;
}
__device__ __forceinline__ float2 unpack2(ull v) {
    float2 r; asm("mov.b64 {%0,%1}, %2;" : "=f"(r.x), "=f"(r.y) : "l"(v)); return r;
}
__device__ __forceinline__ ull ffma2(ull a, ull b, ull c) {
    ull d; asm("fma.rn.f32x2 %0, %1, %2, %3;" : "=l"(d) : "l"(a), "l"(b), "l"(c)); return d;
}
__device__ __forceinline__ ull mul2(ull a, ull b) {
    ull d; asm("mul.rn.f32x2 %0, %1, %2;" : "=l"(d) : "l"(a), "l"(b)); return d;
}
__device__ __forceinline__ float lrelu(float v) {
    return fmaf(0.8f, fmaxf(v, 0.f), 0.2f * v);   // v>0 ? v : 0.2v
}

// ---------------- zero scratch ----------------
__global__ void zero_setup(int n) {
    int i = blockIdx.x * blockDim.x + threadIdx.x;
    if (i < n) { g_cnt[i] = 0; g_fill[i] = 0; }
    if (i < GNUM * HID) g_gsum[i] = 0.f;
    if (i < GNUM) g_gcnt[i] = 0;
}

// ---------------- degree histogram ----------------
__global__ void count_kernel(const int* __restrict__ dstA, int ne) {
    int e = blockIdx.x * blockDim.x + threadIdx.x;
    if (e < ne) atomicAdd(&g_cnt[dstA[e]], 1);
}

// ---------------- exclusive scan (3 kernels) ----------------
__global__ void scanA(int n) {
    __shared__ int s[1024];
    int t = threadIdx.x;
    int i = blockIdx.x * 1024 + t;
    int v = (i < n) ? g_cnt[i] : 0;
    s[t] = v;
    __syncthreads();
    for (int off = 1; off < 1024; off <<= 1) {
        int tmp = (t >= off) ? s[t - off] : 0;
        __syncthreads();
        s[t] += tmp;
        __syncthreads();
    }
    if (i < n) g_off[i] = s[t] - v;
    if (t == 1023) g_part[blockIdx.x] = s[1023];
}

__global__ void scanB(int nb, int n) {
    if (threadIdx.x == 0 && blockIdx.x == 0) {
        int run = 0;
        for (int b = 0; b < nb; b++) { int v = g_part[b]; g_part[b] = run; run += v; }
        g_off[n] = run;
    }
}

__global__ void scanC(int n) {
    int i = blockIdx.x * blockDim.x + threadIdx.x;
    if (i < n) g_off[i] += g_part[i >> 10];
}

// ---------------- CSR fill ----------------
__global__ void fill_kernel(const int* __restrict__ srcA, const int* __restrict__ dstA, int ne) {
    int e = blockIdx.x * blockDim.x + threadIdx.x;
    if (e >= ne) return;
    int d = dstA[e];
    int pos = g_off[d] + atomicAdd(&g_fill[d], 1);
    g_csr_src[pos] = srcA[e];
    g_csr_dst[pos] = d;
    g_csr_eid[pos] = e;
}

// ---------------- gather edge_attr into CSR order (float4 vectorized) ----------------
__global__ void gather_ea_kernel(const float* __restrict__ ea, int ne) {
    int i = blockIdx.x * blockDim.x + threadIdx.x;   // quad index over ne*4
    if (i >= ne * 4) return;
    int pos = i >> 2;
    int q   = i & 3;
    int eid = g_csr_eid[pos];
    const float4* src = reinterpret_cast<const float4*>(ea + (size_t)eid * EDIM);
    float4* dst = reinterpret_cast<float4*>(g_ea_csr + (size_t)pos * EDIM);
    dst[q] = src[q];
}

// ---------------- self-loop attr = mean of incoming edge attrs ----------------
__global__ __launch_bounds__(256) void loop_attr_kernel(int n) {
    int t = threadIdx.x;
    int d = blockIdx.x * 8 + (t >> 5);
    if (d >= n) return;
    int l = t & 31;
    int k = l & 15;
    int half = l >> 4;
    int beg = g_off[d], deg = g_cnt[d];
    float acc = 0.f;
    for (int i = half; i < deg; i += 2) {
        acc += g_ea_csr[(size_t)(beg + i) * EDIM + k];
    }
    acc += __shfl_xor_sync(0xffffffffu, acc, 16);
    if (half == 0) {
        float inv = 1.f / fmaxf((float)deg, 1.f);
        g_loop_attr[d * EDIM + k] = acc * inv;
    }
}

// ---------------- xl = x@Wl + bl ; xr = x@Wr + br  (row-pair f32x2 packed) ----------------
__global__ __launch_bounds__(256) void gemm_kernel(
    const float* __restrict__ x0in,
    const float* __restrict__ Wl, const float* __restrict__ bl,
    const float* __restrict__ Wr, const float* __restrict__ br,
    int n, int layer)
{
    const float* __restrict__ xin = layer ? g_x1 : x0in;
    __shared__ float sWl[64 * 64];
    __shared__ float sWr[64 * 64];
    __shared__ __align__(16) float sx[64 * 68];
    int t = threadIdx.x;
    for (int i = t; i < 4096; i += 256) { sWl[i] = Wl[i]; sWr[i] = Wr[i]; }
    int row0 = blockIdx.x * 64;
    for (int idx = t; idx < 4096; idx += 256) {
        int r = idx >> 6, k = idx & 63;
        int rr = row0 + r;
        sx[k * 68 + r] = (rr < n) ? xin[rr * 64 + k] : 0.f;
    }
    __syncthreads();
    int c = t & 63, rq = t >> 6;
    float blc = bl[c], brc = br[c];
    ull bl2 = pack2(blc, blc), br2 = pack2(brc, brc);
    ull accL[8], accR[8];
#pragma unroll
    for (int j = 0; j < 8; j++) { accL[j] = bl2; accR[j] = br2; }
#pragma unroll 4
    for (int k = 0; k < 64; k++) {
        float wl = sWl[k * 64 + c];
        float wr = sWr[k * 64 + c];
        ull wl2 = pack2(wl, wl), wr2 = pack2(wr, wr);
        const ulonglong2* xp = reinterpret_cast<const ulonglong2*>(&sx[k * 68 + rq * 16]);
#pragma unroll
        for (int q = 0; q < 4; q++) {
            ulonglong2 xv = xp[q];
            accL[q * 2]     = ffma2(xv.x, wl2, accL[q * 2]);
            accL[q * 2 + 1] = ffma2(xv.y, wl2, accL[q * 2 + 1]);
            accR[q * 2]     = ffma2(xv.x, wr2, accR[q * 2]);
            accR[q * 2 + 1] = ffma2(xv.y, wr2, accR[q * 2 + 1]);
        }
    }
#pragma unroll
    for (int j = 0; j < 8; j++) {
        float2 vl = unpack2(accL[j]);
        float2 vr = unpack2(accR[j]);
        int r0 = row0 + rq * 16 + 2 * j;
        if (r0 < n)     { g_xl[r0 * 64 + c] = vl.x;       g_xr[r0 * 64 + c] = vr.x; }
        if (r0 + 1 < n) { g_xl[(r0 + 1) * 64 + c] = vl.y; g_xr[(r0 + 1) * 64 + c] = vr.y; }
    }
}

// ---------------- per-edge pre-reduction score for the lane's two channels ----------
__device__ __forceinline__ float edge_score(
    const ulonglong2* __restrict__ ap, float2 xl2, float2 xr2, float2 at,
    const ull* wp0, const ull* wp1)
{
    ulonglong2 qa = ap[0], qb = ap[1], qc = ap[2], qd = ap[3];
    ull a0 = 0ull, a1 = 0ull;
    a0 = ffma2(qa.x, wp0[0], a0); a1 = ffma2(qa.x, wp1[0], a1);
    a0 = ffma2(qa.y, wp0[1], a0); a1 = ffma2(qa.y, wp1[1], a1);
    a0 = ffma2(qb.x, wp0[2], a0); a1 = ffma2(qb.x, wp1[2], a1);
    a0 = ffma2(qb.y, wp0[3], a0); a1 = ffma2(qb.y, wp1[3], a1);
    a0 = ffma2(qc.x, wp0[4], a0); a1 = ffma2(qc.x, wp1[4], a1);
    a0 = ffma2(qc.y, wp0[5], a0); a1 = ffma2(qc.y, wp1[5], a1);
    a0 = ffma2(qd.x, wp0[6], a0); a1 = ffma2(qd.x, wp1[6], a1);
    a0 = ffma2(qd.y, wp0[7], a0); a1 = ffma2(qd.y, wp1[7], a1);
    float2 h0 = unpack2(a0), h1 = unpack2(a1);
    float e0 = h0.x + h0.y;
    float e1 = h1.x + h1.y;
    float m0 = lrelu(xl2.x + xr2.x + e0);
    float m1 = lrelu(xl2.y + xr2.y + e1);
    return fmaf(at.x, m0, at.y * m1);
}

// ---------------- edge-parallel scoring: warp handles EPW consecutive CSR positions ----
// All edges independent — no loop-carried state, high occupancy, latency-tolerant.
__global__ __launch_bounds__(256) void score_kernel(
    const float* __restrict__ We, const float* __restrict__ att, int ne)
{
    __shared__ float sWe[EDIM * 64];
    __shared__ float satt[64];
    int t = threadIdx.x;
    for (int i = t; i < EDIM * 64; i += 256) sWe[i] = We[i];
    if (t < 64) satt[t] = att[t];
    __syncthreads();
    int l = t & 31, w = t >> 5;

    ull wp0[8], wp1[8];
#pragma unroll
    for (int j = 0; j < 8; j++) {
        float2 wa = *reinterpret_cast<const float2*>(sWe + (2 * j)     * 64 + 2 * l);
        float2 wb = *reinterpret_cast<const float2*>(sWe + (2 * j + 1) * 64 + 2 * l);
        wp0[j] = pack2(wa.x, wb.x);
        wp1[j] = pack2(wa.y, wb.y);
    }
    float2 at = *reinterpret_cast<const float2*>(satt + 2 * l);

    int base = (blockIdx.x * 8 + w) * EPW;
    int end  = min(base + EPW, ne);
#pragma unroll 2
    for (int p = base; p < end; p++) {
        int src = g_csr_src[p];                 // warp-uniform broadcast
        int dst = g_csr_dst[p];                 // warp-uniform; repeats -> L1 hits on xr
        ull xlu = *reinterpret_cast<const ull*>(g_xl + src * 64 + 2 * l);
        ull xru = *reinterpret_cast<const ull*>(g_xr + dst * 64 + 2 * l);
        float pe = edge_score(reinterpret_cast<const ulonglong2*>(g_ea_csr + (size_t)p * EDIM),
                              unpack2(xlu), unpack2(xru), at, wp0, wp1);
        pe += __shfl_xor_sync(0xffffffffu, pe, 1);
        pe += __shfl_xor_sync(0xffffffffu, pe, 2);
        pe += __shfl_xor_sync(0xffffffffu, pe, 4);
        if ((l & 7) == 0) g_score[(size_t)p * 4 + (l >> 3)] = pe;
    }
}

// ---------------- self-loop scores: warp handles EPW consecutive nodes ----------------
__global__ __launch_bounds__(256) void score_self_kernel(
    const float* __restrict__ We, const float* __restrict__ att, int n)
{
    __shared__ float sWe[EDIM * 64];
    __shared__ float satt[64];
    int t = threadIdx.x;
    for (int i = t; i < EDIM * 64; i += 256) sWe[i] = We[i];
    if (t < 64) satt[t] = att[t];
    __syncthreads();
    int l = t & 31, w = t >> 5;

    ull wp0[8], wp1[8];
#pragma unroll
    for (int j = 0; j < 8; j++) {
        float2 wa = *reinterpret_cast<const float2*>(sWe + (2 * j)     * 64 + 2 * l);
        float2 wb = *reinterpret_cast<const float2*>(sWe + (2 * j + 1) * 64 + 2 * l);
        wp0[j] = pack2(wa.x, wb.x);
        wp1[j] = pack2(wa.y, wb.y);
    }
    float2 at = *reinterpret_cast<const float2*>(satt + 2 * l);

    int base = (blockIdx.x * 8 + w) * EPW;
    int end  = min(base + EPW, n);
#pragma unroll 2
    for (int d = base; d < end; d++) {
        ull xlu = *reinterpret_cast<const ull*>(g_xl + d * 64 + 2 * l);
        ull xru = *reinterpret_cast<const ull*>(g_xr + d * 64 + 2 * l);
        float pe = edge_score(reinterpret_cast<const ulonglong2*>(g_loop_attr + d * EDIM),
                              unpack2(xlu), unpack2(xru), at, wp0, wp1);
        pe += __shfl_xor_sync(0xffffffffu, pe, 1);
        pe += __shfl_xor_sync(0xffffffffu, pe, 2);
        pe += __shfl_xor_sync(0xffffffffu, pe, 4);
        if ((l & 7) == 0) g_score_self[d * 4 + (l >> 3)] = pe;
    }
}

// ---------------- softmax + aggregation (warp per node, no per-edge shfl) ----------------
// Pass 1: lane-parallel max. Pass 2: channel-parallel accumulation; z read directly
// per-head from g_score (same-line broadcast), only loop-carried dep is one ffma2.
__global__ __launch_bounds__(256) void aggregate_kernel(const float* __restrict__ bias, int n, int layer)
{
    int t = threadIdx.x;
    int d = blockIdx.x * 8 + (t >> 5);
    if (d >= n) return;
    int l = t & 31;
    int h = l >> 3;
    int beg = g_off[d], deg = g_cnt[d];

    float4 self = *reinterpret_cast<const float4*>(g_score_self + 4 * d);

    // pass 1: max (lane-parallel over contiguous scores)
    float4 mx = self;
    for (int i = l; i < deg; i += 32) {
        float4 sc = *reinterpret_cast<const float4*>(g_score + (size_t)(beg + i) * 4);
        mx.x = fmaxf(mx.x, sc.x); mx.y = fmaxf(mx.y, sc.y);
        mx.z = fmaxf(mx.z, sc.z); mx.w = fmaxf(mx.w, sc.w);
    }
#pragma unroll
    for (int o = 16; o; o >>= 1) {
        mx.x = fmaxf(mx.x, __shfl_xor_sync(0xffffffffu, mx.x, o));
        mx.y = fmaxf(mx.y, __shfl_xor_sync(0xffffffffu, mx.y, o));
        mx.z = fmaxf(mx.z, __shfl_xor_sync(0xffffffffu, mx.z, o));
        mx.w = fmaxf(mx.w, __shfl_xor_sync(0xffffffffu, mx.w, o));
    }
    float mxh   = (h == 0) ? mx.x   : (h == 1) ? mx.y   : (h == 2) ? mx.z   : mx.w;
    float selfh = (h == 0) ? self.x : (h == 1) ? self.y : (h == 2) ? self.z : self.w;

    // pass 2: accumulation; every lane walks all edges (channels split across lanes)
    ull xls = *reinterpret_cast<const ull*>(g_xl + d * 64 + 2 * l);
    float zs = __expf(selfh - mxh);
    float den = zs;
    ull acc = mul2(pack2(zs, zs), xls);
#pragma unroll 4
    for (int i = 0; i < deg; i++) {
        int s = g_csr_src[beg + i];                        // warp-uniform broadcast
        float z = __expf(g_score[(size_t)(beg + i) * 4 + h] - mxh);  // 16B-line broadcast
        ull xlu = *reinterpret_cast<const ull*>(g_xl + s * 64 + 2 * l);
        acc = ffma2(pack2(z, z), xlu, acc);
        den += z;
    }
    float inv = 1.f / den;
    float2 av = unpack2(acc);
    float2 bv = *reinterpret_cast<const float2*>(bias + 2 * l);
    float o0 = fmaxf(fmaf(av.x, inv, bv.x), 0.f);
    float o1 = fmaxf(fmaf(av.y, inv, bv.y), 0.f);
    float* xout = layer ? g_x2 : g_x1;
    *reinterpret_cast<float2*>(xout + d * 64 + 2 * l) = make_float2(o0, o1);
}

// ---------------- mean pool (block-local smem accumulation) ----------------
__global__ __launch_bounds__(256) void pool_kernel(const int* __restrict__ batch, int n)
{
    __shared__ float sacc[GNUM * HID];
    __shared__ int scnt[GNUM];
    int t = threadIdx.x;
    for (int i = t; i < GNUM * HID; i += 256) sacc[i] = 0.f;
    if (t < GNUM) scnt[t] = 0;
    __syncthreads();
    int c = t & 63, sub = t >> 6;
    int start = blockIdx.x * 512;
    int end = min(start + 512, n);
    for (int i = start + sub; i < end; i += 4) {
        int b = batch[i];
        atomicAdd(&sacc[b * HID + c], g_x2[i * HID + c]);
        if (c == 0) atomicAdd(&scnt[b], 1);
    }
    __syncthreads();
    for (int i = t; i < GNUM * HID; i += 256) {
        float v = sacc[i];
        if (v != 0.f) atomicAdd(&g_gsum[i], v);
    }
    if (t < GNUM && scnt[t] != 0) atomicAdd(&g_gcnt[t], scnt[t]);
}

// ---------------- final MLP (one block per graph) ----------------
__global__ __launch_bounds__(128) void mlp_kernel(
    const float* __restrict__ W1, const float* __restrict__ b1,
    const float* __restrict__ W2, const float* __restrict__ b2,
    float* __restrict__ out)
{
    __shared__ float sg[HID];
    __shared__ float sh[OUTD];
    int g = blockIdx.x, t = threadIdx.x;
    if (t < HID) {
        float c = fmaxf((float)g_gcnt[g], 1.f);
        sg[t] = g_gsum[g * HID + t] / c;
    }
    __syncthreads();
    float acc = b1[t];
#pragma unroll
    for (int k = 0; k < HID; k++) acc = fmaf(sg[k], W1[k * OUTD + t], acc);
    sh[t] = fmaxf(acc, 0.f);
    __syncthreads();
    float acc2 = b2[t];
#pragma unroll
    for (int k = 0; k < OUTD; k++) acc2 = fmaf(sh[k], W2[k * OUTD + t], acc2);
    out[g * OUTD + t] = acc2;
}

// ---------------- launch ----------------
extern "C" void kernel_launch(void* const* d_in, const int* in_sizes, int n_in,
                              void* d_out, int out_size)
{
    const float* x0    = (const float*)d_in[0];
    const int*   ei    = (const int*)d_in[1];
    const float* ea    = (const float*)d_in[2];
    const int*   batch = (const int*)d_in[3];

    int n  = in_sizes[0] / HID;      // 100000
    int ne = in_sizes[1] / 2;        // edge_index is (2, E)
    if (n > NMAX) n = NMAX;
    if (ne > EMAX) ne = EMAX;

    const int* srcA = ei;
    const int* dstA = ei + ne;

    const float* Wl[2]   = { (const float*)d_in[4],  (const float*)d_in[11] };
    const float* blv[2]  = { (const float*)d_in[5],  (const float*)d_in[12] };
    const float* Wr[2]   = { (const float*)d_in[6],  (const float*)d_in[13] };
    const float* brv[2]  = { (const float*)d_in[7],  (const float*)d_in[14] };
    const float* We[2]   = { (const float*)d_in[8],  (const float*)d_in[15] };
    const float* att[2]  = { (const float*)d_in[9],  (const float*)d_in[16] };
    const float* bias[2] = { (const float*)d_in[10], (const float*)d_in[17] };
    const float* mW1 = (const float*)d_in[18];
    const float* mb1 = (const float*)d_in[19];
    const float* mW2 = (const float*)d_in[20];
    const float* mb2 = (const float*)d_in[21];
    float* out = (float*)d_out;

    int nb = (n + 1023) / 1024;
    int score_blocks      = (ne + 8 * EPW - 1) / (8 * EPW);
    int score_self_blocks = (n + 8 * EPW - 1) / (8 * EPW);

    zero_setup<<<(n + 255) / 256, 256>>>(n);
    count_kernel<<<(ne + 255) / 256, 256>>>(dstA, ne);
    scanA<<<nb, 1024>>>(n);
    scanB<<<1, 32>>>(nb, n);
    scanC<<<(n + 255) / 256, 256>>>(n);
    fill_kernel<<<(ne + 255) / 256, 256>>>(srcA, dstA, ne);
    gather_ea_kernel<<<(ne * 4 + 255) / 256, 256>>>(ea, ne);
    loop_attr_kernel<<<(n + 7) / 8, 256>>>(n);

    for (int layer = 0; layer < 2; layer++) {
        gemm_kernel<<<(n + 63) / 64, 256>>>(x0, Wl[layer], blv[layer], Wr[layer], brv[layer], n, layer);
        score_kernel<<<score_blocks, 256>>>(We[layer], att[layer], ne);
        score_self_kernel<<<score_self_blocks, 256>>>(We[layer], att[layer], n);
        aggregate_kernel<<<(n + 7) / 8, 256>>>(bias[layer], n, layer);
    }

    pool_kernel<<<(n + 511) / 512, 256>>>(batch, n);
    mlp_kernel<<<GNUM, 128>>>(mW1, mb1, mW2, mb2, out);
}

// round 16
// speedup vs baseline: 1.0706x; 1.0073x over previous
#include <cuda_runtime.h>

#define NMAX 100000
#define EMAX 1600000
#define GNUM 64
#define HID  64
#define EDIM 16
#define OUTD 128
#define EPW  16   // edges (or nodes) per warp in scoring kernels

typedef unsigned long long ull;

// ---------------- static device scratch (no allocations allowed) ----------------
__device__ int   g_cnt[NMAX];
__device__ int   g_fill[NMAX];
__device__ int   g_off[NMAX + 1];
__device__ int   g_part[128];
__device__ int   g_csr_src[EMAX];
__device__ int   g_csr_dst[EMAX];
__device__ int   g_csr_eid[EMAX];
__device__ __align__(16) float g_ea_csr[(size_t)EMAX * EDIM];   // edge_attr in CSR order (streamed, .cs)
__device__ __align__(16) float g_loop_attr[NMAX * EDIM];
__device__ __align__(16) float g_xl[NMAX * HID];
__device__ __align__(16) float g_xr[NMAX * HID];
__device__ __align__(16) float g_x1[NMAX * HID];
__device__ __align__(16) float g_x2[NMAX * HID];
__device__ __align__(16) float g_score[(size_t)EMAX * 4];       // per CSR position, 4 heads
__device__ __align__(16) float g_score_self[NMAX * 4];
__device__ float g_gsum[GNUM * HID];
__device__ int   g_gcnt[GNUM];

// ---------------- f32x2 + streaming-load helpers ----------------
__device__ __forceinline__ ull pack2(float a, float b) {
    ull v; asm("mov.b64 %0, {%1,%2};" : "=l"(v) : "f"(a), "f"(b)); return v;
}
__device__ __forceinline__ float2 unpack2(ull v) {
    float2 r; asm("mov.b64 {%0,%1}, %2;" : "=f"(r.x), "=f"(r.y) : "l"(v)); return r;
}
__device__ __forceinline__ ull ffma2(ull a, ull b, ull c) {
    ull d; asm("fma.rn.f32x2 %0, %1, %2, %3;" : "=l"(d) : "l"(a), "l"(b), "l"(c)); return d;
}
__device__ __forceinline__ ull mul2(ull a, ull b) {
    ull d; asm("mul.rn.f32x2 %0, %1, %2;" : "=l"(d) : "l"(a), "l"(b)); return d;
}
__device__ __forceinline__ float lrelu(float v) {
    return fmaf(0.8f, fmaxf(v, 0.f), 0.2f * v);   // v>0 ? v : 0.2v
}
// evict-first vector load: keep streams from thrashing L2
__device__ __forceinline__ ulonglong2 ldcs_u64x2(const ulonglong2* p) {
    ulonglong2 r;
    asm("ld.global.cs.v2.u64 {%0,%1}, [%2];" : "=l"(r.x), "=l"(r.y) : "l"(p));
    return r;
}
__device__ __forceinline__ float4 ldcs_f4(const float4* p) {
    float4 r;
    asm("ld.global.cs.v4.f32 {%0,%1,%2,%3}, [%4];"
        : "=f"(r.x), "=f"(r.y), "=f"(r.z), "=f"(r.w) : "l"(p));
    return r;
}
__device__ __forceinline__ void stcs_f4(float4* p, float4 v) {
    asm("st.global.cs.v4.f32 [%0], {%1,%2,%3,%4};"
        :: "l"(p), "f"(v.x), "f"(v.y), "f"(v.z), "f"(v.w) : "memory");
}
__device__ __forceinline__ float ldcs_f(const float* p) {
    float r; asm("ld.global.cs.f32 %0, [%1];" : "=f"(r) : "l"(p)); return r;
}

// ---------------- zero scratch ----------------
__global__ void zero_setup(int n) {
    int i = blockIdx.x * blockDim.x + threadIdx.x;
    if (i < n) { g_cnt[i] = 0; g_fill[i] = 0; }
    if (i < GNUM * HID) g_gsum[i] = 0.f;
    if (i < GNUM) g_gcnt[i] = 0;
}

// ---------------- degree histogram ----------------
__global__ void count_kernel(const int* __restrict__ dstA, int ne) {
    int e = blockIdx.x * blockDim.x + threadIdx.x;
    if (e < ne) atomicAdd(&g_cnt[dstA[e]], 1);
}

// ---------------- exclusive scan (3 kernels) ----------------
__global__ void scanA(int n) {
    __shared__ int s[1024];
    int t = threadIdx.x;
    int i = blockIdx.x * 1024 + t;
    int v = (i < n) ? g_cnt[i] : 0;
    s[t] = v;
    __syncthreads();
    for (int off = 1; off < 1024; off <<= 1) {
        int tmp = (t >= off) ? s[t - off] : 0;
        __syncthreads();
        s[t] += tmp;
        __syncthreads();
    }
    if (i < n) g_off[i] = s[t] - v;
    if (t == 1023) g_part[blockIdx.x] = s[1023];
}

__global__ void scanB(int nb, int n) {
    if (threadIdx.x == 0 && blockIdx.x == 0) {
        int run = 0;
        for (int b = 0; b < nb; b++) { int v = g_part[b]; g_part[b] = run; run += v; }
        g_off[n] = run;
    }
}

__global__ void scanC(int n) {
    int i = blockIdx.x * blockDim.x + threadIdx.x;
    if (i < n) g_off[i] += g_part[i >> 10];
}

// ---------------- CSR fill ----------------
__global__ void fill_kernel(const int* __restrict__ srcA, const int* __restrict__ dstA, int ne) {
    int e = blockIdx.x * blockDim.x + threadIdx.x;
    if (e >= ne) return;
    int d = dstA[e];
    int pos = g_off[d] + atomicAdd(&g_fill[d], 1);
    g_csr_src[pos] = srcA[e];
    g_csr_dst[pos] = d;
    g_csr_eid[pos] = e;
}

// ---------------- gather edge_attr into CSR order (streaming loads/stores) ----------------
__global__ void gather_ea_kernel(const float* __restrict__ ea, int ne) {
    int i = blockIdx.x * blockDim.x + threadIdx.x;   // quad index over ne*4
    if (i >= ne * 4) return;
    int pos = i >> 2;
    int q   = i & 3;
    int eid = g_csr_eid[pos];
    const float4* src = reinterpret_cast<const float4*>(ea + (size_t)eid * EDIM);
    float4* dst = reinterpret_cast<float4*>(g_ea_csr + (size_t)pos * EDIM);
    stcs_f4(dst + q, ldcs_f4(src + q));
}

// ---------------- self-loop attr = mean of incoming edge attrs (streaming reads) ----
__global__ __launch_bounds__(256) void loop_attr_kernel(int n) {
    int t = threadIdx.x;
    int d = blockIdx.x * 8 + (t >> 5);
    if (d >= n) return;
    int l = t & 31;
    int k = l & 15;
    int half = l >> 4;
    int beg = g_off[d], deg = g_cnt[d];
    float acc = 0.f;
    for (int i = half; i < deg; i += 2) {
        acc += ldcs_f(&g_ea_csr[(size_t)(beg + i) * EDIM + k]);
    }
    acc += __shfl_xor_sync(0xffffffffu, acc, 16);
    if (half == 0) {
        float inv = 1.f / fmaxf((float)deg, 1.f);
        g_loop_attr[d * EDIM + k] = acc * inv;
    }
}

// ---------------- xl = x@Wl + bl ; xr = x@Wr + br  (row-pair f32x2 packed) ----------------
__global__ __launch_bounds__(256) void gemm_kernel(
    const float* __restrict__ x0in,
    const float* __restrict__ Wl, const float* __restrict__ bl,
    const float* __restrict__ Wr, const float* __restrict__ br,
    int n, int layer)
{
    const float* __restrict__ xin = layer ? g_x1 : x0in;
    __shared__ float sWl[64 * 64];
    __shared__ float sWr[64 * 64];
    __shared__ __align__(16) float sx[64 * 68];
    int t = threadIdx.x;
    for (int i = t; i < 4096; i += 256) { sWl[i] = Wl[i]; sWr[i] = Wr[i]; }
    int row0 = blockIdx.x * 64;
    for (int idx = t; idx < 4096; idx += 256) {
        int r = idx >> 6, k = idx & 63;
        int rr = row0 + r;
        sx[k * 68 + r] = (rr < n) ? xin[rr * 64 + k] : 0.f;
    }
    __syncthreads();
    int c = t & 63, rq = t >> 6;
    float blc = bl[c], brc = br[c];
    ull bl2 = pack2(blc, blc), br2 = pack2(brc, brc);
    ull accL[8], accR[8];
#pragma unroll
    for (int j = 0; j < 8; j++) { accL[j] = bl2; accR[j] = br2; }
#pragma unroll 4
    for (int k = 0; k < 64; k++) {
        float wl = sWl[k * 64 + c];
        float wr = sWr[k * 64 + c];
        ull wl2 = pack2(wl, wl), wr2 = pack2(wr, wr);
        const ulonglong2* xp = reinterpret_cast<const ulonglong2*>(&sx[k * 68 + rq * 16]);
#pragma unroll
        for (int q = 0; q < 4; q++) {
            ulonglong2 xv = xp[q];
            accL[q * 2]     = ffma2(xv.x, wl2, accL[q * 2]);
            accL[q * 2 + 1] = ffma2(xv.y, wl2, accL[q * 2 + 1]);
            accR[q * 2]     = ffma2(xv.x, wr2, accR[q * 2]);
            accR[q * 2 + 1] = ffma2(xv.y, wr2, accR[q * 2 + 1]);
        }
    }
#pragma unroll
    for (int j = 0; j < 8; j++) {
        float2 vl = unpack2(accL[j]);
        float2 vr = unpack2(accR[j]);
        int r0 = row0 + rq * 16 + 2 * j;
        if (r0 < n)     { g_xl[r0 * 64 + c] = vl.x;       g_xr[r0 * 64 + c] = vr.x; }
        if (r0 + 1 < n) { g_xl[(r0 + 1) * 64 + c] = vl.y; g_xr[(r0 + 1) * 64 + c] = vr.y; }
    }
}

// ---------------- per-edge pre-reduction score for the lane's two channels ----------
// qa..qd: the edge's 16 attrs as f32x2 pairs (already loaded by caller).
__device__ __forceinline__ float edge_score(
    ulonglong2 qa, ulonglong2 qb, ulonglong2 qc, ulonglong2 qd,
    float2 xl2, float2 xr2, float2 at,
    const ull* wp0, const ull* wp1)
{
    ull a0 = 0ull, a1 = 0ull;
    a0 = ffma2(qa.x, wp0[0], a0); a1 = ffma2(qa.x, wp1[0], a1);
    a0 = ffma2(qa.y, wp0[1], a0); a1 = ffma2(qa.y, wp1[1], a1);
    a0 = ffma2(qb.x, wp0[2], a0); a1 = ffma2(qb.x, wp1[2], a1);
    a0 = ffma2(qb.y, wp0[3], a0); a1 = ffma2(qb.y, wp1[3], a1);
    a0 = ffma2(qc.x, wp0[4], a0); a1 = ffma2(qc.x, wp1[4], a1);
    a0 = ffma2(qc.y, wp0[5], a0); a1 = ffma2(qc.y, wp1[5], a1);
    a0 = ffma2(qd.x, wp0[6], a0); a1 = ffma2(qd.x, wp1[6], a1);
    a0 = ffma2(qd.y, wp0[7], a0); a1 = ffma2(qd.y, wp1[7], a1);
    float2 h0 = unpack2(a0), h1 = unpack2(a1);
    float e0 = h0.x + h0.y;
    float e1 = h1.x + h1.y;
    float m0 = lrelu(xl2.x + xr2.x + e0);
    float m1 = lrelu(xl2.y + xr2.y + e1);
    return fmaf(at.x, m0, at.y * m1);
}

// ---------------- edge-parallel scoring: warp handles EPW consecutive CSR positions ----
// ea_csr read with .cs (evict-first) so the 102MB stream does not evict xl/xr from L2.
__global__ __launch_bounds__(256) void score_kernel(
    const float* __restrict__ We, const float* __restrict__ att, int ne)
{
    __shared__ float sWe[EDIM * 64];
    __shared__ float satt[64];
    int t = threadIdx.x;
    for (int i = t; i < EDIM * 64; i += 256) sWe[i] = We[i];
    if (t < 64) satt[t] = att[t];
    __syncthreads();
    int l = t & 31, w = t >> 5;

    ull wp0[8], wp1[8];
#pragma unroll
    for (int j = 0; j < 8; j++) {
        float2 wa = *reinterpret_cast<const float2*>(sWe + (2 * j)     * 64 + 2 * l);
        float2 wb = *reinterpret_cast<const float2*>(sWe + (2 * j + 1) * 64 + 2 * l);
        wp0[j] = pack2(wa.x, wb.x);
        wp1[j] = pack2(wa.y, wb.y);
    }
    float2 at = *reinterpret_cast<const float2*>(satt + 2 * l);

    int base = (blockIdx.x * 8 + w) * EPW;
    int end  = min(base + EPW, ne);
#pragma unroll 2
    for (int p = base; p < end; p++) {
        int src = g_csr_src[p];                 // warp-uniform broadcast
        int dst = g_csr_dst[p];                 // warp-uniform; repeats -> L1 hits on xr
        ull xlu = *reinterpret_cast<const ull*>(g_xl + src * 64 + 2 * l);
        ull xru = *reinterpret_cast<const ull*>(g_xr + dst * 64 + 2 * l);
        const ulonglong2* ap = reinterpret_cast<const ulonglong2*>(g_ea_csr + (size_t)p * EDIM);
        ulonglong2 qa = ldcs_u64x2(ap + 0);
        ulonglong2 qb = ldcs_u64x2(ap + 1);
        ulonglong2 qc = ldcs_u64x2(ap + 2);
        ulonglong2 qd = ldcs_u64x2(ap + 3);
        float pe = edge_score(qa, qb, qc, qd, unpack2(xlu), unpack2(xru), at, wp0, wp1);
        pe += __shfl_xor_sync(0xffffffffu, pe, 1);
        pe += __shfl_xor_sync(0xffffffffu, pe, 2);
        pe += __shfl_xor_sync(0xffffffffu, pe, 4);
        if ((l & 7) == 0) g_score[(size_t)p * 4 + (l >> 3)] = pe;
    }
}

// ---------------- self-loop scores: warp handles EPW consecutive nodes ----------------
__global__ __launch_bounds__(256) void score_self_kernel(
    const float* __restrict__ We, const float* __restrict__ att, int n)
{
    __shared__ float sWe[EDIM * 64];
    __shared__ float satt[64];
    int t = threadIdx.x;
    for (int i = t; i < EDIM * 64; i += 256) sWe[i] = We[i];
    if (t < 64) satt[t] = att[t];
    __syncthreads();
    int l = t & 31, w = t >> 5;

    ull wp0[8], wp1[8];
#pragma unroll
    for (int j = 0; j < 8; j++) {
        float2 wa = *reinterpret_cast<const float2*>(sWe + (2 * j)     * 64 + 2 * l);
        float2 wb = *reinterpret_cast<const float2*>(sWe + (2 * j + 1) * 64 + 2 * l);
        wp0[j] = pack2(wa.x, wb.x);
        wp1[j] = pack2(wa.y, wb.y);
    }
    float2 at = *reinterpret_cast<const float2*>(satt + 2 * l);

    int base = (blockIdx.x * 8 + w) * EPW;
    int end  = min(base + EPW, n);
#pragma unroll 2
    for (int d = base; d < end; d++) {
        ull xlu = *reinterpret_cast<const ull*>(g_xl + d * 64 + 2 * l);
        ull xru = *reinterpret_cast<const ull*>(g_xr + d * 64 + 2 * l);
        const ulonglong2* ap = reinterpret_cast<const ulonglong2*>(g_loop_attr + d * EDIM);
        ulonglong2 qa = ap[0], qb = ap[1], qc = ap[2], qd = ap[3];
        float pe = edge_score(qa, qb, qc, qd, unpack2(xlu), unpack2(xru), at, wp0, wp1);
        pe += __shfl_xor_sync(0xffffffffu, pe, 1);
        pe += __shfl_xor_sync(0xffffffffu, pe, 2);
        pe += __shfl_xor_sync(0xffffffffu, pe, 4);
        if ((l & 7) == 0) g_score_self[d * 4 + (l >> 3)] = pe;
    }
}

// ---------------- softmax + aggregation (warp per node, no per-edge shfl) ----------------
__global__ __launch_bounds__(256) void aggregate_kernel(const float* __restrict__ bias, int n, int layer)
{
    int t = threadIdx.x;
    int d = blockIdx.x * 8 + (t >> 5);
    if (d >= n) return;
    int l = t & 31;
    int h = l >> 3;
    int beg = g_off[d], deg = g_cnt[d];

    float4 self = *reinterpret_cast<const float4*>(g_score_self + 4 * d);

    // pass 1: max (lane-parallel over contiguous scores)
    float4 mx = self;
    for (int i = l; i < deg; i += 32) {
        float4 sc = *reinterpret_cast<const float4*>(g_score + (size_t)(beg + i) * 4);
        mx.x = fmaxf(mx.x, sc.x); mx.y = fmaxf(mx.y, sc.y);
        mx.z = fmaxf(mx.z, sc.z); mx.w = fmaxf(mx.w, sc.w);
    }
#pragma unroll
    for (int o = 16; o; o >>= 1) {
        mx.x = fmaxf(mx.x, __shfl_xor_sync(0xffffffffu, mx.x, o));
        mx.y = fmaxf(mx.y, __shfl_xor_sync(0xffffffffu, mx.y, o));
        mx.z = fmaxf(mx.z, __shfl_xor_sync(0xffffffffu, mx.z, o));
        mx.w = fmaxf(mx.w, __shfl_xor_sync(0xffffffffu, mx.w, o));
    }
    float mxh   = (h == 0) ? mx.x   : (h == 1) ? mx.y   : (h == 2) ? mx.z   : mx.w;
    float selfh = (h == 0) ? self.x : (h == 1) ? self.y : (h == 2) ? self.z : self.w;

    // pass 2: accumulation; every lane walks all edges (channels split across lanes)
    ull xls = *reinterpret_cast<const ull*>(g_xl + d * 64 + 2 * l);
    float zs = __expf(selfh - mxh);
    float den = zs;
    ull acc = mul2(pack2(zs, zs), xls);
#pragma unroll 4
    for (int i = 0; i < deg; i++) {
        int s = g_csr_src[beg + i];                        // warp-uniform broadcast
        float z = __expf(g_score[(size_t)(beg + i) * 4 + h] - mxh);  // 16B-line broadcast
        ull xlu = *reinterpret_cast<const ull*>(g_xl + s * 64 + 2 * l);
        acc = ffma2(pack2(z, z), xlu, acc);
        den += z;
    }
    float inv = 1.f / den;
    float2 av = unpack2(acc);
    float2 bv = *reinterpret_cast<const float2*>(bias + 2 * l);
    float o0 = fmaxf(fmaf(av.x, inv, bv.x), 0.f);
    float o1 = fmaxf(fmaf(av.y, inv, bv.y), 0.f);
    float* xout = layer ? g_x2 : g_x1;
    *reinterpret_cast<float2*>(xout + d * 64 + 2 * l) = make_float2(o0, o1);
}

// ---------------- mean pool (block-local smem accumulation) ----------------
__global__ __launch_bounds__(256) void pool_kernel(const int* __restrict__ batch, int n)
{
    __shared__ float sacc[GNUM * HID];
    __shared__ int scnt[GNUM];
    int t = threadIdx.x;
    for (int i = t; i < GNUM * HID; i += 256) sacc[i] = 0.f;
    if (t < GNUM) scnt[t] = 0;
    __syncthreads();
    int c = t & 63, sub = t >> 6;
    int start = blockIdx.x * 512;
    int end = min(start + 512, n);
    for (int i = start + sub; i < end; i += 4) {
        int b = batch[i];
        atomicAdd(&sacc[b * HID + c], g_x2[i * HID + c]);
        if (c == 0) atomicAdd(&scnt[b], 1);
    }
    __syncthreads();
    for (int i = t; i < GNUM * HID; i += 256) {
        float v = sacc[i];
        if (v != 0.f) atomicAdd(&g_gsum[i], v);
    }
    if (t < GNUM && scnt[t] != 0) atomicAdd(&g_gcnt[t], scnt[t]);
}

// ---------------- final MLP (one block per graph) ----------------
__global__ __launch_bounds__(128) void mlp_kernel(
    const float* __restrict__ W1, const float* __restrict__ b1,
    const float* __restrict__ W2, const float* __restrict__ b2,
    float* __restrict__ out)
{
    __shared__ float sg[HID];
    __shared__ float sh[OUTD];
    int g = blockIdx.x, t = threadIdx.x;
    if (t < HID) {
        float c = fmaxf((float)g_gcnt[g], 1.f);
        sg[t] = g_gsum[g * HID + t] / c;
    }
    __syncthreads();
    float acc = b1[t];
#pragma unroll
    for (int k = 0; k < HID; k++) acc = fmaf(sg[k], W1[k * OUTD + t], acc);
    sh[t] = fmaxf(acc, 0.f);
    __syncthreads();
    float acc2 = b2[t];
#pragma unroll
    for (int k = 0; k < OUTD; k++) acc2 = fmaf(sh[k], W2[k * OUTD + t], acc2);
    out[g * OUTD + t] = acc2;
}

// ---------------- launch ----------------
extern "C" void kernel_launch(void* const* d_in, const int* in_sizes, int n_in,
                              void* d_out, int out_size)
{
    const float* x0    = (const float*)d_in[0];
    const int*   ei    = (const int*)d_in[1];
    const float* ea    = (const float*)d_in[2];
    const int*   batch = (const int*)d_in[3];

    int n  = in_sizes[0] / HID;      // 100000
    int ne = in_sizes[1] / 2;        // edge_index is (2, E)
    if (n > NMAX) n = NMAX;
    if (ne > EMAX) ne = EMAX;

    const int* srcA = ei;
    const int* dstA = ei + ne;

    const float* Wl[2]   = { (const float*)d_in[4],  (const float*)d_in[11] };
    const float* blv[2]  = { (const float*)d_in[5],  (const float*)d_in[12] };
    const float* Wr[2]   = { (const float*)d_in[6],  (const float*)d_in[13] };
    const float* brv[2]  = { (const float*)d_in[7],  (const float*)d_in[14] };
    const float* We[2]   = { (const float*)d_in[8],  (const float*)d_in[15] };
    const float* att[2]  = { (const float*)d_in[9],  (const float*)d_in[16] };
    const float* bias[2] = { (const float*)d_in[10], (const float*)d_in[17] };
    const float* mW1 = (const float*)d_in[18];
    const float* mb1 = (const float*)d_in[19];
    const float* mW2 = (const float*)d_in[20];
    const float* mb2 = (const float*)d_in[21];
    float* out = (float*)d_out;

    int nb = (n + 1023) / 1024;
    int score_blocks      = (ne + 8 * EPW - 1) / (8 * EPW);
    int score_self_blocks = (n + 8 * EPW - 1) / (8 * EPW);

    zero_setup<<<(n + 255) / 256, 256>>>(n);
    count_kernel<<<(ne + 255) / 256, 256>>>(dstA, ne);
    scanA<<<nb, 1024>>>(n);
    scanB<<<1, 32>>>(nb, n);
    scanC<<<(n + 255) / 256, 256>>>(n);
    fill_kernel<<<(ne + 255) / 256, 256>>>(srcA, dstA, ne);
    gather_ea_kernel<<<(ne * 4 + 255) / 256, 256>>>(ea, ne);
    loop_attr_kernel<<<(n + 7) / 8, 256>>>(n);

    for (int layer = 0; layer < 2; layer++) {
        gemm_kernel<<<(n + 63) / 64, 256>>>(x0, Wl[layer], blv[layer], Wr[layer], brv[layer], n, layer);
        score_kernel<<<score_blocks, 256>>>(We[layer], att[layer], ne);
        score_self_kernel<<<score_self_blocks, 256>>>(We[layer], att[layer], n);
        aggregate_kernel<<<(n + 7) / 8, 256>>>(bias[layer], n, layer);
    }

    pool_kernel<<<(n + 511) / 512, 256>>>(batch, n);
    mlp_kernel<<<GNUM, 128>>>(mW1, mb1, mW2, mb2, out);
}